// round 14
// baseline (speedup 1.0000x reference)
#include <cuda_runtime.h>
#include <cuda_fp16.h>
#include <cstdint>

// LSTMDecoder on GB300 (sm_103 ptxas -> mma.sync path).
// R14: R11 core (proven at the mma.sync issue floor: wall == 28.35K HMMA/SM
// x 16cyc/SMSP == 55.9us/step) + STREAMED output transpose: tiles at
// t in {11,23,35,47} write out[p][t-11..t] (12 floats = 3 float4) for their
// 4096 points, hiding 3/4 of the old finalize's 768MB under the
// issue-bound GEMM (DRAM was at 3%). Visibility: own writes (plane t+1) +
// cumulative release/acquire chain through g_flags (planes <= t).
// Single merged prep launch. No separate finalize kernel.

#define HDIM   1024
#define NBATCH 2048
#define LSTEPS 48
#define TM     128
#define TN     128          // 32 j x 4 gates, interleaved j*4+g
#define TJ     32
#define BK     64           // 64 fp16 = 128B rows
#define NSTAGE 3
#define KTILES (HDIM / BK)  // 16
#define NTHR   256
#define NWORK  296          // persistent CTAs = 2/SM x 148
#define TPS    512          // tiles per step (16 x * 32 y)

#define SM_BIAS 0
#define SM_PIPE 1024
#define A_BYTES (TM * BK * 2)                       // 16384
#define B_BYTES (TN * BK * 2)                       // 16384
#define STAGE_BYTES (A_BYTES + B_BYTES)             // 32768
#define SMEM_TOTAL (SM_PIPE + NSTAGE * STAGE_BYTES) // 99328 (2 CTAs/SM)

#define EPS 33
#define SWZ(o) ((o) ^ (((o) >> 3) & 0x70))

__device__ __half g_hs[LSTEPS + 1][NBATCH * HDIM]; // fp16 h history (in=0)
__device__ float  g_c[NBATCH * HDIM];              // cell state (fp32)
__device__ __half g_Wr[4 * HDIM * HDIM];           // reordered fp16 W: row j*4+g
__device__ float  g_biasr[4 * HDIM];               // reordered bias
__device__ int    g_flags[LSTEPS][16][32];         // tile (t,x,y) done

// ---------- helpers ----------
__device__ __forceinline__ uint32_t smem_u32(const void* p) {
    uint32_t a;
    asm("{ .reg .u64 t; cvta.to.shared.u64 t, %1; cvt.u32.u64 %0, t; }" : "=r"(a) : "l"(p));
    return a;
}
__device__ __forceinline__ void cpa16(uint32_t dst, const void* src) {
    asm volatile("cp.async.cg.shared.global [%0], [%1], 16;" :: "r"(dst), "l"(src));
}
#define CP_COMMIT() asm volatile("cp.async.commit_group;" ::: "memory")
#define CP_WAIT(n)  asm volatile("cp.async.wait_group %0;" :: "n"(n) : "memory")

__device__ __forceinline__ int ld_acq(const int* p) {
    int v;
    asm volatile("ld.global.acquire.gpu.b32 %0, [%1];" : "=r"(v) : "l"(p));
    return v;
}
__device__ __forceinline__ void st_rel(int* p, int v) {
    asm volatile("st.global.release.gpu.b32 [%0], %1;" :: "l"(p), "r"(v) : "memory");
}
__device__ __forceinline__ void wait_pair(const int* f) {
    while (ld_acq(f) == 0) { __nanosleep(128); }
    while (ld_acq(f + 1) == 0) { __nanosleep(128); }
}
__device__ __forceinline__ void ldm_x4(uint32_t* r, uint32_t addr) {
    asm volatile("ldmatrix.sync.aligned.m8n8.x4.shared.b16 {%0,%1,%2,%3}, [%4];"
                 : "=r"(r[0]), "=r"(r[1]), "=r"(r[2]), "=r"(r[3]) : "r"(addr));
}
__device__ __forceinline__ void mma16(float* c, const uint32_t* a, const uint32_t* b) {
    asm("mma.sync.aligned.m16n8k16.row.col.f32.f16.f16.f32 "
        "{%0,%1,%2,%3}, {%4,%5,%6,%7}, {%8,%9}, {%0,%1,%2,%3};"
        : "+f"(c[0]), "+f"(c[1]), "+f"(c[2]), "+f"(c[3])
        : "r"(a[0]), "r"(a[1]), "r"(a[2]), "r"(a[3]), "r"(b[0]), "r"(b[1]));
}
__device__ __forceinline__ float sigm(float x) {
    return __fdividef(1.0f, 1.0f + __expf(-x));
}
__device__ __forceinline__ float tanh_(float x) {
    return __fdividef(2.0f, 1.0f + __expf(-2.0f * x)) - 1.0f;
}

// ---------- single merged prep kernel ----------
// grid 4096 x 256: all blocks convert W (1M float4); blocks 0..2047 also
// convert h_in (512K float4); blocks 2048..2063 bias; 2064..2159 flags.
__global__ void prep_all(const float* __restrict__ h_in,
                         const float* __restrict__ W,
                         const float* __restrict__ bi,
                         const float* __restrict__ bh) {
    int idx = blockIdx.x * 256 + threadIdx.x;
    {   // W reorder + fp16 convert
        int rn = idx >> 8, k4 = idx & 255;
        int j = rn >> 2, g = rn & 3;
        float4 v = ((const float4*)W)[(size_t)(g * HDIM + j) * (HDIM / 4) + k4];
        __half2 lo = __floats2half2_rn(v.x, v.y);
        __half2 hi = __floats2half2_rn(v.z, v.w);
        ((uint2*)g_Wr)[(size_t)rn * (HDIM / 4) + k4] =
            make_uint2(*(uint32_t*)&lo, *(uint32_t*)&hi);
    }
    if (blockIdx.x < 2048) {     // h convert
        float4 v = ((const float4*)h_in)[idx];
        __half2 lo = __floats2half2_rn(v.x, v.y);
        __half2 hi = __floats2half2_rn(v.z, v.w);
        ((uint2*)g_hs[0])[idx] = make_uint2(*(uint32_t*)&lo, *(uint32_t*)&hi);
    } else if (blockIdx.x < 2064) {   // bias: 4096 elems
        int b = (blockIdx.x - 2048) * 256 + threadIdx.x;
        int j = b >> 2, g = b & 3;
        g_biasr[b] = bi[g * HDIM + j] + bh[g * HDIM + j];
    } else if (blockIdx.x < 2160) {   // flags: 24576 ints
        int f = (blockIdx.x - 2064) * 256 + threadIdx.x;
        ((int*)g_flags)[f] = 0;
    }
}

// ---------- persistent kernel: 48 steps + streamed output transpose ----------
__global__ __launch_bounds__(NTHR, 2)
void lstm_all(float* __restrict__ out) {
    extern __shared__ char smc[];
    float* sbias = (float*)(smc + SM_BIAS);
    const uint32_t smb = smem_u32(smc);

    const int tid = threadIdx.x;
    const int w = tid >> 5, lane = tid & 31;
    const int gid = lane >> 2, tig = lane & 3;
    const int wm = w & 3, wn = w >> 2;          // 4 x 2 warp grid, 32x64 tiles
    const int rit = lane & 7;
    const int tg  = lane >> 3;

    // ldmatrix lane addressing, relative to stage base; ^ (kk<<5) per k16
    uint32_t ra[2];
#pragma unroll
    for (int mf = 0; mf < 2; mf++) {
        int arow = wm * 32 + mf * 16 + (tg & 1) * 8 + rit;
        ra[mf] = SM_PIPE + (uint32_t)arow * 128 + ((uint32_t)((tg >> 1) ^ rit) << 4);
    }
    uint32_t rb[4];
#pragma unroll
    for (int p = 0; p < 4; p++) {
        int brow = wn * 64 + (2 * p + (tg >> 1)) * 8 + rit;
        rb[p] = SM_PIPE + A_BYTES + (uint32_t)brow * 128 +
                ((uint32_t)((tg & 1) ^ rit) << 4);
    }

#pragma unroll 1
    for (int gidx = blockIdx.x; gidx < LSTEPS * TPS; gidx += NWORK) {
        const int t = gidx >> 9;
        const int r = gidx & 511;
        const int x = r >> 5;             // m-block 0..15
        const int y = r & 31;             // n-block 0..31
        const int m0 = x * TM;
        const int n0 = y * TN;
        const int jblk = y * TJ;

        const __half* __restrict__ hsrc = g_hs[t];
        __half* __restrict__ hdst = g_hs[t + 1];
        const int* fcol = (t > 0) ? &g_flags[t - 1][x][0] : (const int*)0;

        if (tid < TN) sbias[tid] = g_biasr[n0 + tid];

        auto load_tile = [&](int kt, int s) {
            const uint32_t abase = smb + SM_PIPE + s * STAGE_BYTES;
            const uint32_t bbase = abase + A_BYTES;
            const __half* asrc = hsrc + (size_t)m0 * HDIM + kt * BK;
            const __half* bsrc = g_Wr + (size_t)n0 * HDIM + kt * BK;
#pragma unroll
            for (int p = 0; p < 4; p++) {       // A: 128 rows x 128B
                int idx = tid + p * NTHR;
                int row = idx >> 3, ch = idx & 7;
                uint32_t off = (uint32_t)(row * 128 + ch * 16);
                cpa16(abase + SWZ(off), asrc + (size_t)row * HDIM + ch * 8);
            }
#pragma unroll
            for (int p = 0; p < 4; p++) {       // B: 128 rows x 128B
                int idx = tid + p * NTHR;
                int row = idx >> 3, ch = idx & 7;
                uint32_t off = (uint32_t)(row * 128 + ch * 16);
                cpa16(bbase + SWZ(off), bsrc + (size_t)row * HDIM + ch * 8);
            }
        };

        // prologue: tiles 0,1 (wait producer slices for t>0)
        if (t > 0) wait_pair(fcol + 0);
        load_tile(0, 0); CP_COMMIT();
        if (t > 0) wait_pair(fcol + 2);
        load_tile(1, 1); CP_COMMIT();
        __syncthreads();   // sbias visible; prev-tile smem reads done

        // accumulators, bias folded in
        float acc[2][8][4];
#pragma unroll
        for (int mf = 0; mf < 2; mf++)
#pragma unroll
            for (int nf = 0; nf < 8; nf++) {
                int c = wn * 64 + nf * 8 + 2 * tig;
                float b0 = sbias[c], b1 = sbias[c + 1];
                acc[mf][nf][0] = b0; acc[mf][nf][1] = b1;
                acc[mf][nf][2] = b0; acc[mf][nf][3] = b1;
            }

        uint32_t af[2][2][4];   // [buf][mf][frag]
        uint32_t bf[2][4];      // [buf][pair frag]

#pragma unroll 1
        for (int kt = 0; kt < KTILES; kt++) {
            const int s = kt % NSTAGE;
            CP_WAIT(1);
            __syncthreads();
            if (kt + 2 < KTILES) {
                if (t > 0) wait_pair(fcol + 2 * (kt + 2));
                load_tile(kt + 2, (kt + 2) % NSTAGE);
            }
            CP_COMMIT();

            const uint32_t sb = smb + (uint32_t)s * STAGE_BYTES;
            const uint32_t a0 = sb + ra[0], a1 = sb + ra[1];
            const uint32_t bb0 = sb + rb[0], bb1 = sb + rb[1];
            const uint32_t bb2 = sb + rb[2], bb3 = sb + rb[3];

            // prime this tile's pipeline: A(kk0), B(kk0,p0)
            ldm_x4(af[0][0], a0);
            ldm_x4(af[0][1], a1);
            ldm_x4(bf[0], bb0);

#pragma unroll
            for (int kk = 0; kk < 4; kk++) {
                const int ab = kk & 1;
                const uint32_t xc = (uint32_t)kk << 5;
                const uint32_t xn = (uint32_t)((kk + 1) & 3) << 5;
#pragma unroll
                for (int p = 0; p < 4; p++) {
                    const int pb = (kk * 4 + p) & 1;
                    // ---- prefetch next group's fragments ----
                    if (p == 0) {
                        ldm_x4(bf[pb ^ 1], bb1 ^ xc);
                    } else if (p == 1) {
                        ldm_x4(bf[pb ^ 1], bb2 ^ xc);
                    } else if (p == 2) {
                        ldm_x4(bf[pb ^ 1], bb3 ^ xc);
                        if (kk < 3) {
                            ldm_x4(af[ab ^ 1][0], a0 ^ xn);
                            ldm_x4(af[ab ^ 1][1], a1 ^ xn);
                        }
                    } else if (kk < 3) { // p==3
                        ldm_x4(bf[pb ^ 1], bb0 ^ xn);
                    }
                    // ---- 4 MMAs on register-resident fragments ----
                    mma16(acc[0][2 * p],     af[ab][0], &bf[pb][0]);
                    mma16(acc[0][2 * p + 1], af[ab][0], &bf[pb][2]);
                    mma16(acc[1][2 * p],     af[ab][1], &bf[pb][0]);
                    mma16(acc[1][2 * p + 1], af[ab][1], &bf[pb][2]);
                }
            }
        }
        CP_WAIT(0);
        __syncthreads();  // all MMAs done before smem reuse

        // ---- epilogue: shfl-pair gate fusion -> smem staging ----
        float* P  = (float*)(smc + SM_PIPE);
        float* F  = P + TM * EPS;
        float* OG = F + TM * EPS;
        const int odd = tig & 1;

#pragma unroll
        for (int mf = 0; mf < 2; mf++)
#pragma unroll
            for (int nf = 0; nf < 8; nf++) {
                float c0 = acc[mf][nf][0], c1 = acc[mf][nf][1];
                float c2 = acc[mf][nf][2], c3 = acc[mf][nf][3];
                float e0 = __shfl_xor_sync(0xFFFFFFFFu, c0, 1);
                float e1 = __shfl_xor_sync(0xFFFFFFFFu, c1, 1);
                float e2 = __shfl_xor_sync(0xFFFFFFFFu, c2, 1);
                float e3 = __shfl_xor_sync(0xFFFFFFFFu, c3, 1);
                float zi = odd ? e2 : c0;
                float zf = odd ? e3 : c1;
                float zg = odd ? c2 : e0;
                float zo = odd ? c3 : e1;
                int row = wm * 32 + mf * 16 + gid + (odd ? 8 : 0);
                int jl  = wn * 16 + nf * 2 + (tig >> 1);
                float ig = sigm(zi), fg = sigm(zf), gg = tanh_(zg), og = sigm(zo);
                P[row * EPS + jl]  = ig * gg;
                F[row * EPS + jl]  = fg;
                OG[row * EPS + jl] = og;
            }
        __syncthreads();

        // ---- coalesced state update ----
        const bool first = (t == 0);
#pragma unroll
        for (int it = 0; it < (TM * TJ) / NTHR; it++) {
            int idx = it * NTHR + tid;
            int row = idx >> 5, j = idx & 31;
            size_t g = (size_t)(m0 + row) * HDIM + jblk + j;
            float cold = first ? 0.0f : g_c[g];
            float cnew = F[row * EPS + j] * cold + P[row * EPS + j];
            float h = OG[row * EPS + j] * tanh_(cnew);
            g_c[g]  = cnew;
            hdst[g] = __float2half_rn(h);
        }

        // ---- publish ----
        __threadfence();
        __syncthreads();
        if (tid == 0) st_rel(&g_flags[t][x][y], 1);

        // ---- streamed output transpose: 12-step chunk every 12 steps ----
        // out[p][tc..tc+11] <- g_hs[tc+1..tc+12][p], tc = t-11.
        // Planes <= t visible via acquire chain (flags[t-1][x][*] acquired
        // above, inductively back to t=0); plane t+1 written by this tile.
        if ((t % 12) == 11) {
            const int tc = t - 11;
#pragma unroll 1
            for (int it = 0; it < (TM * TJ) / NTHR; it++) {
                int idx = it * NTHR + tid;
                int row = idx >> 5, j = idx & 31;
                size_t p = (size_t)(m0 + row) * HDIM + jblk + j;
                float4* o = (float4*)(out + p * LSTEPS + tc);
#pragma unroll
                for (int q = 0; q < 3; q++) {
                    float4 v;
                    v.x = __half2float(g_hs[tc + 4 * q + 1][p]);
                    v.y = __half2float(g_hs[tc + 4 * q + 2][p]);
                    v.z = __half2float(g_hs[tc + 4 * q + 3][p]);
                    v.w = __half2float(g_hs[tc + 4 * q + 4][p]);
                    o[q] = v;
                }
            }
        }
    }
}

extern "C" void kernel_launch(void* const* d_in, const int* in_sizes, int n_in,
                              void* d_out, int out_size) {
    const float* h_in = (const float*)d_in[0];
    const float* W    = (const float*)d_in[1];
    const float* b_ih = (const float*)d_in[2];
    const float* b_hh = (const float*)d_in[3];

    cudaFuncSetAttribute(lstm_all, cudaFuncAttributeMaxDynamicSharedMemorySize, SMEM_TOTAL);

    prep_all<<<4096, 256>>>(h_in, W, b_ih, b_hh);

    lstm_all<<<NWORK, NTHR, SMEM_TOTAL>>>((float*)d_out);
}

// round 15
// speedup vs baseline: 1.0556x; 1.0556x over previous
#include <cuda_runtime.h>
#include <cuda_fp16.h>
#include <cstdint>

// LSTMDecoder on GB300 (sm_103 ptxas -> mma.sync path).
// R15: R11 GEMM core (at the mma.sync issue floor: 55.9us/step) with the
// output transpose as SEPARATE work-list tiles interleaved between step
// segments: after each 8-step segment c, 512 standalone transpose tiles
// write out[p][8c..8c+7] (dep: one flag acquire -> cumulative visibility).
// Unlike R13/R14 (transpose fused into compute tiles -> convoy delays),
// these tiles are scheduled work: memory-bound tiles run while other
// workers' GEMMs keep the tensor pipes fed. Only the last chunk tails.
// fp16 m16n8k16 fp32-accum, ldmatrix.x4, BK=64, 128x128 CTA tiles, 32x64
// warp tiles, 2 CTAs/SM, register fragment pipeline, per-(t,x,y) flags.

#define HDIM   1024
#define NBATCH 2048
#define LSTEPS 48
#define TM     128
#define TN     128          // 32 j x 4 gates, interleaved j*4+g
#define TJ     32
#define BK     64           // 64 fp16 = 128B rows
#define NSTAGE 3
#define KTILES (HDIM / BK)  // 16
#define NTHR   256
#define NWORK  296          // persistent CTAs = 2/SM x 148
#define TPS    512          // tiles per step (16 x * 32 y)
#define SEG    8            // steps per segment
#define NSEG   (LSTEPS / SEG)                   // 6
#define SEGTILES (SEG * TPS + TPS)              // 4608: 8x512 compute + 512 transpose
#define TOTTILES (NSEG * SEGTILES)              // 27648

#define SM_BIAS 0
#define SM_PIPE 1024
#define A_BYTES (TM * BK * 2)                       // 16384
#define B_BYTES (TN * BK * 2)                       // 16384
#define STAGE_BYTES (A_BYTES + B_BYTES)             // 32768
#define SMEM_TOTAL (SM_PIPE + NSTAGE * STAGE_BYTES) // 99328 (2 CTAs/SM)

#define EPS 33
#define SWZ(o) ((o) ^ (((o) >> 3) & 0x70))

__device__ __half g_hs[LSTEPS + 1][NBATCH * HDIM]; // fp16 h history (in=0)
__device__ float  g_c[NBATCH * HDIM];              // cell state (fp32)
__device__ __half g_Wr[4 * HDIM * HDIM];           // reordered fp16 W: row j*4+g
__device__ float  g_biasr[4 * HDIM];               // reordered bias
__device__ int    g_flags[LSTEPS][16][32];         // tile (t,x,y) done

// ---------- helpers ----------
__device__ __forceinline__ uint32_t smem_u32(const void* p) {
    uint32_t a;
    asm("{ .reg .u64 t; cvta.to.shared.u64 t, %1; cvt.u32.u64 %0, t; }" : "=r"(a) : "l"(p));
    return a;
}
__device__ __forceinline__ void cpa16(uint32_t dst, const void* src) {
    asm volatile("cp.async.cg.shared.global [%0], [%1], 16;" :: "r"(dst), "l"(src));
}
#define CP_COMMIT() asm volatile("cp.async.commit_group;" ::: "memory")
#define CP_WAIT(n)  asm volatile("cp.async.wait_group %0;" :: "n"(n) : "memory")

__device__ __forceinline__ int ld_acq(const int* p) {
    int v;
    asm volatile("ld.global.acquire.gpu.b32 %0, [%1];" : "=r"(v) : "l"(p));
    return v;
}
__device__ __forceinline__ void st_rel(int* p, int v) {
    asm volatile("st.global.release.gpu.b32 [%0], %1;" :: "l"(p), "r"(v) : "memory");
}
__device__ __forceinline__ void wait_flag(const int* f) {
    while (ld_acq(f) == 0) { __nanosleep(128); }
}
__device__ __forceinline__ void wait_pair(const int* f) {
    while (ld_acq(f) == 0) { __nanosleep(128); }
    while (ld_acq(f + 1) == 0) { __nanosleep(128); }
}
__device__ __forceinline__ void ldm_x4(uint32_t* r, uint32_t addr) {
    asm volatile("ldmatrix.sync.aligned.m8n8.x4.shared.b16 {%0,%1,%2,%3}, [%4];"
                 : "=r"(r[0]), "=r"(r[1]), "=r"(r[2]), "=r"(r[3]) : "r"(addr));
}
__device__ __forceinline__ void mma16(float* c, const uint32_t* a, const uint32_t* b) {
    asm("mma.sync.aligned.m16n8k16.row.col.f32.f16.f16.f32 "
        "{%0,%1,%2,%3}, {%4,%5,%6,%7}, {%8,%9}, {%0,%1,%2,%3};"
        : "+f"(c[0]), "+f"(c[1]), "+f"(c[2]), "+f"(c[3])
        : "r"(a[0]), "r"(a[1]), "r"(a[2]), "r"(a[3]), "r"(b[0]), "r"(b[1]));
}
__device__ __forceinline__ float sigm(float x) {
    return __fdividef(1.0f, 1.0f + __expf(-x));
}
__device__ __forceinline__ float tanh_(float x) {
    return __fdividef(2.0f, 1.0f + __expf(-2.0f * x)) - 1.0f;
}

// ---------- single merged prep kernel ----------
__global__ void prep_all(const float* __restrict__ h_in,
                         const float* __restrict__ W,
                         const float* __restrict__ bi,
                         const float* __restrict__ bh) {
    int idx = blockIdx.x * 256 + threadIdx.x;
    {   // W reorder + fp16 convert
        int rn = idx >> 8, k4 = idx & 255;
        int j = rn >> 2, g = rn & 3;
        float4 v = ((const float4*)W)[(size_t)(g * HDIM + j) * (HDIM / 4) + k4];
        __half2 lo = __floats2half2_rn(v.x, v.y);
        __half2 hi = __floats2half2_rn(v.z, v.w);
        ((uint2*)g_Wr)[(size_t)rn * (HDIM / 4) + k4] =
            make_uint2(*(uint32_t*)&lo, *(uint32_t*)&hi);
    }
    if (blockIdx.x < 2048) {     // h convert
        float4 v = ((const float4*)h_in)[idx];
        __half2 lo = __floats2half2_rn(v.x, v.y);
        __half2 hi = __floats2half2_rn(v.z, v.w);
        ((uint2*)g_hs[0])[idx] = make_uint2(*(uint32_t*)&lo, *(uint32_t*)&hi);
    } else if (blockIdx.x < 2064) {   // bias: 4096 elems
        int b = (blockIdx.x - 2048) * 256 + threadIdx.x;
        int j = b >> 2, g = b & 3;
        g_biasr[b] = bi[g * HDIM + j] + bh[g * HDIM + j];
    } else if (blockIdx.x < 2160) {   // flags: 24576 ints
        int f = (blockIdx.x - 2064) * 256 + threadIdx.x;
        ((int*)g_flags)[f] = 0;
    }
}

// ---------- persistent kernel: 48 steps + interleaved transpose tiles ----------
__global__ __launch_bounds__(NTHR, 2)
void lstm_all(float* __restrict__ out) {
    extern __shared__ char smc[];
    float* sbias = (float*)(smc + SM_BIAS);
    const uint32_t smb = smem_u32(smc);

    const int tid = threadIdx.x;
    const int w = tid >> 5, lane = tid & 31;
    const int gid = lane >> 2, tig = lane & 3;
    const int wm = w & 3, wn = w >> 2;          // 4 x 2 warp grid, 32x64 tiles
    const int rit = lane & 7;
    const int tg  = lane >> 3;

    // ldmatrix lane addressing, relative to stage base; ^ (kk<<5) per k16
    uint32_t ra[2];
#pragma unroll
    for (int mf = 0; mf < 2; mf++) {
        int arow = wm * 32 + mf * 16 + (tg & 1) * 8 + rit;
        ra[mf] = SM_PIPE + (uint32_t)arow * 128 + ((uint32_t)((tg >> 1) ^ rit) << 4);
    }
    uint32_t rb[4];
#pragma unroll
    for (int p = 0; p < 4; p++) {
        int brow = wn * 64 + (2 * p + (tg >> 1)) * 8 + rit;
        rb[p] = SM_PIPE + A_BYTES + (uint32_t)brow * 128 +
                ((uint32_t)((tg & 1) ^ rit) << 4);
    }

#pragma unroll 1
    for (int gidx = blockIdx.x; gidx < TOTTILES; gidx += NWORK) {
        const int seg = gidx / SEGTILES;
        const int off = gidx - seg * SEGTILES;

        // ================= transpose tile =================
        if (off >= SEG * TPS) {
            const int r = off - SEG * TPS;
            const int x = r >> 5, y = r & 31;
            const int m0 = x * TM, jblk = y * TJ;
            const int tc = seg * SEG;     // out columns tc..tc+7
            // one flag: cumulative acquire chain covers planes <= tc+8
            // for this (x, j-range); plane tc+8 (our j's) written by the
            // flagged tile itself.
            wait_flag(&g_flags[tc + SEG - 1][x][y]);
#pragma unroll 1
            for (int it = 0; it < (TM * TJ) / NTHR; it++) {
                int idx = it * NTHR + tid;
                int row = idx >> 5, j = idx & 31;
                size_t p = (size_t)(m0 + row) * HDIM + jblk + j;
                float4 v0, v1;
                v0.x = __half2float(g_hs[tc + 1][p]);
                v0.y = __half2float(g_hs[tc + 2][p]);
                v0.z = __half2float(g_hs[tc + 3][p]);
                v0.w = __half2float(g_hs[tc + 4][p]);
                v1.x = __half2float(g_hs[tc + 5][p]);
                v1.y = __half2float(g_hs[tc + 6][p]);
                v1.z = __half2float(g_hs[tc + 7][p]);
                v1.w = __half2float(g_hs[tc + 8][p]);
                float4* o = (float4*)(out + p * LSTEPS + tc);
                o[0] = v0;
                o[1] = v1;
            }
            continue;
        }

        // ================= compute tile =================
        const int t = seg * SEG + (off >> 9);
        const int r = off & 511;
        const int x = r >> 5;             // m-block 0..15
        const int y = r & 31;             // n-block 0..31
        const int m0 = x * TM;
        const int n0 = y * TN;
        const int jblk = y * TJ;

        const __half* __restrict__ hsrc = g_hs[t];
        __half* __restrict__ hdst = g_hs[t + 1];
        const int* fcol = (t > 0) ? &g_flags[t - 1][x][0] : (const int*)0;

        if (tid < TN) sbias[tid] = g_biasr[n0 + tid];

        auto load_tile = [&](int kt, int s) {
            const uint32_t abase = smb + SM_PIPE + s * STAGE_BYTES;
            const uint32_t bbase = abase + A_BYTES;
            const __half* asrc = hsrc + (size_t)m0 * HDIM + kt * BK;
            const __half* bsrc = g_Wr + (size_t)n0 * HDIM + kt * BK;
#pragma unroll
            for (int p = 0; p < 4; p++) {       // A: 128 rows x 128B
                int idx = tid + p * NTHR;
                int row = idx >> 3, ch = idx & 7;
                uint32_t off2 = (uint32_t)(row * 128 + ch * 16);
                cpa16(abase + SWZ(off2), asrc + (size_t)row * HDIM + ch * 8);
            }
#pragma unroll
            for (int p = 0; p < 4; p++) {       // B: 128 rows x 128B
                int idx = tid + p * NTHR;
                int row = idx >> 3, ch = idx & 7;
                uint32_t off2 = (uint32_t)(row * 128 + ch * 16);
                cpa16(bbase + SWZ(off2), bsrc + (size_t)row * HDIM + ch * 8);
            }
        };

        // prologue: tiles 0,1 (wait producer slices for t>0)
        if (t > 0) wait_pair(fcol + 0);
        load_tile(0, 0); CP_COMMIT();
        if (t > 0) wait_pair(fcol + 2);
        load_tile(1, 1); CP_COMMIT();
        __syncthreads();   // sbias visible; prev-tile smem reads done

        // accumulators, bias folded in
        float acc[2][8][4];
#pragma unroll
        for (int mf = 0; mf < 2; mf++)
#pragma unroll
            for (int nf = 0; nf < 8; nf++) {
                int c = wn * 64 + nf * 8 + 2 * tig;
                float b0 = sbias[c], b1 = sbias[c + 1];
                acc[mf][nf][0] = b0; acc[mf][nf][1] = b1;
                acc[mf][nf][2] = b0; acc[mf][nf][3] = b1;
            }

        uint32_t af[2][2][4];   // [buf][mf][frag]
        uint32_t bf[2][4];      // [buf][pair frag]

#pragma unroll 1
        for (int kt = 0; kt < KTILES; kt++) {
            const int s = kt % NSTAGE;
            CP_WAIT(1);
            __syncthreads();
            if (kt + 2 < KTILES) {
                if (t > 0) wait_pair(fcol + 2 * (kt + 2));
                load_tile(kt + 2, (kt + 2) % NSTAGE);
            }
            CP_COMMIT();

            const uint32_t sb = smb + (uint32_t)s * STAGE_BYTES;
            const uint32_t a0 = sb + ra[0], a1 = sb + ra[1];
            const uint32_t bb0 = sb + rb[0], bb1 = sb + rb[1];
            const uint32_t bb2 = sb + rb[2], bb3 = sb + rb[3];

            // prime this tile's pipeline: A(kk0), B(kk0,p0)
            ldm_x4(af[0][0], a0);
            ldm_x4(af[0][1], a1);
            ldm_x4(bf[0], bb0);

#pragma unroll
            for (int kk = 0; kk < 4; kk++) {
                const int ab = kk & 1;
                const uint32_t xc = (uint32_t)kk << 5;
                const uint32_t xn = (uint32_t)((kk + 1) & 3) << 5;
#pragma unroll
                for (int p = 0; p < 4; p++) {
                    const int pb = (kk * 4 + p) & 1;
                    // ---- prefetch next group's fragments ----
                    if (p == 0) {
                        ldm_x4(bf[pb ^ 1], bb1 ^ xc);
                    } else if (p == 1) {
                        ldm_x4(bf[pb ^ 1], bb2 ^ xc);
                    } else if (p == 2) {
                        ldm_x4(bf[pb ^ 1], bb3 ^ xc);
                        if (kk < 3) {
                            ldm_x4(af[ab ^ 1][0], a0 ^ xn);
                            ldm_x4(af[ab ^ 1][1], a1 ^ xn);
                        }
                    } else if (kk < 3) { // p==3
                        ldm_x4(bf[pb ^ 1], bb0 ^ xn);
                    }
                    // ---- 4 MMAs on register-resident fragments ----
                    mma16(acc[0][2 * p],     af[ab][0], &bf[pb][0]);
                    mma16(acc[0][2 * p + 1], af[ab][0], &bf[pb][2]);
                    mma16(acc[1][2 * p],     af[ab][1], &bf[pb][0]);
                    mma16(acc[1][2 * p + 1], af[ab][1], &bf[pb][2]);
                }
            }
        }
        CP_WAIT(0);
        __syncthreads();  // all MMAs done before smem reuse

        // ---- epilogue: shfl-pair gate fusion -> smem staging ----
        float* P  = (float*)(smc + SM_PIPE);
        float* F  = P + TM * EPS;
        float* OG = F + TM * EPS;
        const int odd = tig & 1;

#pragma unroll
        for (int mf = 0; mf < 2; mf++)
#pragma unroll
            for (int nf = 0; nf < 8; nf++) {
                float c0 = acc[mf][nf][0], c1 = acc[mf][nf][1];
                float c2 = acc[mf][nf][2], c3 = acc[mf][nf][3];
                float e0 = __shfl_xor_sync(0xFFFFFFFFu, c0, 1);
                float e1 = __shfl_xor_sync(0xFFFFFFFFu, c1, 1);
                float e2 = __shfl_xor_sync(0xFFFFFFFFu, c2, 1);
                float e3 = __shfl_xor_sync(0xFFFFFFFFu, c3, 1);
                float zi = odd ? e2 : c0;
                float zf = odd ? e3 : c1;
                float zg = odd ? c2 : e0;
                float zo = odd ? c3 : e1;
                int row = wm * 32 + mf * 16 + gid + (odd ? 8 : 0);
                int jl  = wn * 16 + nf * 2 + (tig >> 1);
                float ig = sigm(zi), fg = sigm(zf), gg = tanh_(zg), og = sigm(zo);
                P[row * EPS + jl]  = ig * gg;
                F[row * EPS + jl]  = fg;
                OG[row * EPS + jl] = og;
            }
        __syncthreads();

        // ---- coalesced state update ----
        const bool first = (t == 0);
#pragma unroll
        for (int it = 0; it < (TM * TJ) / NTHR; it++) {
            int idx = it * NTHR + tid;
            int row = idx >> 5, j = idx & 31;
            size_t g = (size_t)(m0 + row) * HDIM + jblk + j;
            float cold = first ? 0.0f : g_c[g];
            float cnew = F[row * EPS + j] * cold + P[row * EPS + j];
            float h = OG[row * EPS + j] * tanh_(cnew);
            g_c[g]  = cnew;
            hdst[g] = __float2half_rn(h);
        }

        // ---- publish ----
        __threadfence();
        __syncthreads();
        if (tid == 0) st_rel(&g_flags[t][x][y], 1);
    }
}

extern "C" void kernel_launch(void* const* d_in, const int* in_sizes, int n_in,
                              void* d_out, int out_size) {
    const float* h_in = (const float*)d_in[0];
    const float* W    = (const float*)d_in[1];
    const float* b_ih = (const float*)d_in[2];
    const float* b_hh = (const float*)d_in[3];

    cudaFuncSetAttribute(lstm_all, cudaFuncAttributeMaxDynamicSharedMemorySize, SMEM_TOTAL);

    prep_all<<<4096, 256>>>(h_in, W, b_ih, b_hh);

    lstm_all<<<NWORK, NTHR, SMEM_TOTAL>>>((float*)d_out);
}